// round 16
// baseline (speedup 1.0000x reference)
#include <cuda_runtime.h>
#include <cuda_fp16.h>
#include <math_constants.h>

#define NNODES 100000
#define FIN 512
#define F1 16
#define F2P 8   // 7 padded to 8

// ---------------- scratch (no allocations allowed) ----------------
__device__ int g_cnt[NNODES];   // in-degree (excl self-loop); zero at load,
                                // re-zeroed by k_logsoftmax each call.
__device__ __align__(16) float  g_xw[NNODES * F1];   // raw f32 gemm output
__device__ __align__(16) __half g_y1[NNODES * F1];   // f16 gather src (32B/row)
__device__ __align__(16) __half g_acc1[NNODES * F1]; // f16 RED accumulator
__device__ __align__(16) __half g_y2[NNODES * F2P];  // 16B/row
__device__ __align__(16) __half g_acc2[NNODES * F2P];
__device__ int g_is64;   // edge dtype flag (1 = int64, 0 = int32)

// ---------------- helpers ----------------
__device__ __forceinline__ void red_v4h(__half* p, uint4 v) {
    asm volatile("red.global.add.noftz.v4.f16x2 [%0], {%1, %2, %3, %4};"
                 :: "l"(p), "r"(v.x), "r"(v.y), "r"(v.z), "r"(v.w) : "memory");
}
__device__ __forceinline__ unsigned long long fma2(unsigned long long a,
                                                   unsigned long long b,
                                                   unsigned long long c) {
    unsigned long long d;
    asm("fma.rn.f32x2 %0, %1, %2, %3;" : "=l"(d) : "l"(a), "l"(b), "l"(c));
    return d;
}
__device__ __forceinline__ unsigned long long mul2(unsigned long long a,
                                                   unsigned long long b) {
    unsigned long long d;
    asm("mul.rn.f32x2 %0, %1, %2;" : "=l"(d) : "l"(a), "l"(b));
    return d;
}
__device__ __forceinline__ unsigned long long pack2(float x) {
    unsigned long long d;
    unsigned xi = __float_as_uint(x);
    asm("mov.b64 %0, {%1, %1};" : "=l"(d) : "r"(xi));
    return d;
}
__device__ __forceinline__ unsigned h2_from_u64(unsigned long long v) {
    unsigned lo, hi;
    asm("mov.b64 {%0, %1}, %2;" : "=r"(lo), "=r"(hi) : "l"(v));
    __half2 h = __floats2half2_rn(__uint_as_float(lo), __uint_as_float(hi));
    return *(unsigned*)&h;
}

// Layout: planar [all sources | all targets], E entries per block.
__device__ __forceinline__ void load_edge(const void* ei, int E, int e,
                                          int& r, int& c) {
    if (g_is64) {
        const long long* p = (const long long*)ei;
        r = (int)p[e];
        c = (int)p[(size_t)E + e];
    } else {
        const int* p = (const int*)ei;
        r = p[e];
        c = p[(size_t)E + e];
    }
}
__device__ __forceinline__ void load_edge_pair(const void* ei, int E, int e0,
                                               int& r0, int& c0, int& r1, int& c1) {
    if (g_is64) {
        const long long* p = (const long long*)ei;
        longlong2 rv = *(const longlong2*)(p + e0);
        longlong2 cv = *(const longlong2*)(p + (size_t)E + e0);
        r0 = (int)rv.x; r1 = (int)rv.y;
        c0 = (int)cv.x; c1 = (int)cv.y;
    } else {
        const int* p = (const int*)ei;
        int2 rv = *(const int2*)(p + e0);
        int2 cv = *(const int2*)(p + (size_t)E + e0);
        r0 = rv.x; r1 = rv.y;
        c0 = cv.x; c1 = cv.y;
    }
}

// ---------------- kernels ----------------

// FRONT kernel: block-role split.
//   blocks [0, gbG):      xw = x @ W1 (f32, thread-per-row, W in smem)
//   blocks [gbG, gbG+gbD): in-degree histogram (int atomics), with per-block
//                          dtype probe (8 int64 samples; block gbG publishes
//                          g_is64 for later launches).
// Deg work overlaps the DRAM-bound gemm mainloop on-chip.
__global__ void __launch_bounds__(256) k_front(const float* __restrict__ x,
                                               const float* __restrict__ W,
                                               const void* __restrict__ ei,
                                               int n, int E, int gbG) {
    __shared__ __align__(16) unsigned long long sW[FIN * 8];  // 32 KB
    if ((int)blockIdx.x < gbG) {
        // ---- GEMM role ----
        {
            const ulonglong2* Wv = (const ulonglong2*)W;
            ulonglong2* sWv = (ulonglong2*)sW;
            for (int i = threadIdx.x; i < FIN * 4; i += 256) sWv[i] = Wv[i];
        }
        __syncthreads();
        int row = blockIdx.x * 256 + threadIdx.x;
        if (row >= n) return;

        unsigned long long acc[8];
#pragma unroll
        for (int f = 0; f < 8; f++) acc[f] = 0ull;

        const float4* xr = (const float4*)(x + (size_t)row * FIN);
#pragma unroll 2
        for (int k4 = 0; k4 < FIN / 4; k4++) {
            float4 xv = xr[k4];
#pragma unroll
            for (int d = 0; d < 4; d++) {
                float xk = (d == 0) ? xv.x : (d == 1) ? xv.y : (d == 2) ? xv.z : xv.w;
                unsigned long long xx = pack2(xk);
                const ulonglong2* wp = (const ulonglong2*)&sW[(k4 * 4 + d) * 8];
                ulonglong2 wa = wp[0], wb = wp[1];
                acc[0] = fma2(xx, wa.x, acc[0]);
                acc[1] = fma2(xx, wa.y, acc[1]);
                acc[2] = fma2(xx, wb.x, acc[2]);
                acc[3] = fma2(xx, wb.y, acc[3]);
                ulonglong2 wc = wp[2], wd = wp[3];
                acc[4] = fma2(xx, wc.x, acc[4]);
                acc[5] = fma2(xx, wc.y, acc[5]);
                acc[6] = fma2(xx, wd.x, acc[6]);
                acc[7] = fma2(xx, wd.y, acc[7]);
            }
        }
        ulonglong2* o = (ulonglong2*)(g_xw + (size_t)row * F1);
#pragma unroll
        for (int q = 0; q < 4; q++) {
            ulonglong2 v; v.x = acc[q * 2]; v.y = acc[q * 2 + 1];
            o[q] = v;
        }
    } else {
        // ---- DEG role ----
        __shared__ int s_is64;
        if (threadIdx.x == 0) {
            const long long* p = (const long long*)ei;
            int ok = 1;
#pragma unroll
            for (int j = 0; j < 8; j++) {
                long long v = p[j];
                if (v < 0 || v >= (long long)n) { ok = 0; break; }
            }
            s_is64 = ok;
            if ((int)blockIdx.x == gbG) g_is64 = ok;  // publish for later kernels
        }
        __syncthreads();
        int e = (blockIdx.x - gbG) * 256 + threadIdx.x;
        if (e >= E) return;
        int c;
        if (s_is64) c = (int)((const long long*)ei)[(size_t)E + e];
        else        c = ((const int*)ei)[(size_t)E + e];
        if ((unsigned)c >= (unsigned)n) return;
        atomicAdd(&g_cnt[c], 1);
    }
}

// scale: y1 = rsqrt(cnt+1) * xw in f16, dual-stored (acc init = self-loop).
__global__ void k_scale(int n) {
    int row = blockIdx.x * blockDim.x + threadIdx.x;
    if (row >= n) return;
    unsigned long long dd = pack2(rsqrtf((float)g_cnt[row] + 1.0f));
    const ulonglong2* xw = (const ulonglong2*)(g_xw + (size_t)row * F1);
    uint4 a, b;
    {
        ulonglong2 v0 = xw[0], v1 = xw[1];
        a.x = h2_from_u64(mul2(v0.x, dd));
        a.y = h2_from_u64(mul2(v0.y, dd));
        a.z = h2_from_u64(mul2(v1.x, dd));
        a.w = h2_from_u64(mul2(v1.y, dd));
        ulonglong2 v2 = xw[2], v3 = xw[3];
        b.x = h2_from_u64(mul2(v2.x, dd));
        b.y = h2_from_u64(mul2(v2.y, dd));
        b.z = h2_from_u64(mul2(v3.x, dd));
        b.w = h2_from_u64(mul2(v3.y, dd));
    }
    uint4* o1 = (uint4*)(g_y1 + (size_t)row * F1);
    uint4* o2 = (uint4*)(g_acc1 + (size_t)row * F1);
    o1[0] = a; o1[1] = b;
    o2[0] = a; o2[1] = b;
}

// layer-1 edge scatter, 2 edges/thread, f16 transport.
__global__ void k_scatter1(const void* __restrict__ ei, int E, int n) {
    int t = blockIdx.x * blockDim.x + threadIdx.x;
    int e0 = t * 2;
    if (e0 >= E) return;
    int r0 = -1, c0 = -1, r1 = -1, c1 = -1;
    if (((E & 1) == 0) && e0 + 1 < E) {
        load_edge_pair(ei, E, e0, r0, c0, r1, c1);
    } else {
        load_edge(ei, E, e0, r0, c0);
        if (e0 + 1 < E) load_edge(ei, E, e0 + 1, r1, c1);
    }
    if ((unsigned)r0 < (unsigned)n && (unsigned)c0 < (unsigned)n) {
        const uint4* src = (const uint4*)(g_y1 + (size_t)r0 * F1);
        __half* dst = g_acc1 + (size_t)c0 * F1;
        uint4 a = src[0], b = src[1];
        red_v4h(dst, a);
        red_v4h(dst + 8, b);
    }
    if ((unsigned)r1 < (unsigned)n && (unsigned)c1 < (unsigned)n) {
        const uint4* src = (const uint4*)(g_y1 + (size_t)r1 * F1);
        __half* dst = g_acc1 + (size_t)c1 * F1;
        uint4 a = src[0], b = src[1];
        red_v4h(dst, a);
        red_v4h(dst + 8, b);
    }
}

// h = relu(b1 + dinv*acc1); y2 = dinv*(h @ W2) in f16; dual store.
__global__ void k_layer2(const float* __restrict__ W2,
                         const float* __restrict__ b1, int n) {
    int i = blockIdx.x * blockDim.x + threadIdx.x;
    if (i >= n) return;
    float di = rsqrtf((float)g_cnt[i] + 1.0f);
    const uint4* p = (const uint4*)(g_acc1 + (size_t)i * F1);
    uint4 pa = p[0], pb = p[1];
    float h[16];
    {
        unsigned u[8] = {pa.x, pa.y, pa.z, pa.w, pb.x, pb.y, pb.z, pb.w};
#pragma unroll
        for (int q = 0; q < 8; q++) {
            float2 v = __half22float2(*(__half2*)&u[q]);
            h[q * 2 + 0] = fmaxf(__ldg(&b1[q * 2 + 0]) + di * v.x, 0.f);
            h[q * 2 + 1] = fmaxf(__ldg(&b1[q * 2 + 1]) + di * v.y, 0.f);
        }
    }
    float s[7] = {0.f, 0.f, 0.f, 0.f, 0.f, 0.f, 0.f};
#pragma unroll
    for (int k = 0; k < 16; k++) {
        float hk = h[k];
#pragma unroll
        for (int f = 0; f < 7; f++) s[f] += hk * __ldg(&W2[k * 7 + f]);
    }
    uint4 o;
    {
        __half2 h0 = __floats2half2_rn(di * s[0], di * s[1]);
        __half2 h1 = __floats2half2_rn(di * s[2], di * s[3]);
        __half2 h2 = __floats2half2_rn(di * s[4], di * s[5]);
        __half2 h3 = __floats2half2_rn(di * s[6], 0.f);
        o.x = *(unsigned*)&h0; o.y = *(unsigned*)&h1;
        o.z = *(unsigned*)&h2; o.w = *(unsigned*)&h3;
    }
    *(uint4*)(g_y2 + (size_t)i * F2P) = o;
    *(uint4*)(g_acc2 + (size_t)i * F2P) = o;
}

// layer-2 edge scatter, 2 edges/thread.
__global__ void k_scatter2(const void* __restrict__ ei, int E, int n) {
    int t = blockIdx.x * blockDim.x + threadIdx.x;
    int e0 = t * 2;
    if (e0 >= E) return;
    int r0 = -1, c0 = -1, r1 = -1, c1 = -1;
    if (((E & 1) == 0) && e0 + 1 < E) {
        load_edge_pair(ei, E, e0, r0, c0, r1, c1);
    } else {
        load_edge(ei, E, e0, r0, c0);
        if (e0 + 1 < E) load_edge(ei, E, e0 + 1, r1, c1);
    }
    if ((unsigned)r0 < (unsigned)n && (unsigned)c0 < (unsigned)n) {
        uint4 v = *(const uint4*)(g_y2 + (size_t)r0 * F2P);
        red_v4h(g_acc2 + (size_t)c0 * F2P, v);
    }
    if ((unsigned)r1 < (unsigned)n && (unsigned)c1 < (unsigned)n) {
        uint4 v = *(const uint4*)(g_y2 + (size_t)r1 * F2P);
        red_v4h(g_acc2 + (size_t)c1 * F2P, v);
    }
}

// w = b2 + dinv*acc2; log_softmax; then RE-ZERO g_cnt for the next replay.
__global__ void k_logsoftmax(const float* __restrict__ b2,
                             float* __restrict__ out, int n) {
    int i = blockIdx.x * blockDim.x + threadIdx.x;
    if (i >= n) return;
    float di = rsqrtf((float)g_cnt[i] + 1.0f);
    g_cnt[i] = 0;   // restore zero-state for next graph replay (deterministic)
    uint4 v = *(const uint4*)(g_acc2 + (size_t)i * F2P);
    unsigned u[4] = {v.x, v.y, v.z, v.w};
    float w[8];
#pragma unroll
    for (int q = 0; q < 4; q++) {
        float2 f = __half22float2(*(__half2*)&u[q]);
        w[q * 2 + 0] = f.x;
        w[q * 2 + 1] = f.y;
    }
#pragma unroll
    for (int f = 0; f < 7; f++) w[f] = __ldg(&b2[f]) + di * w[f];
    float m = w[0];
#pragma unroll
    for (int f = 1; f < 7; f++) m = fmaxf(m, w[f]);
    float s = 0.f;
#pragma unroll
    for (int f = 0; f < 7; f++) s += expf(w[f] - m);
    float l = logf(s);
    float* o = out + (size_t)i * 7;
#pragma unroll
    for (int f = 0; f < 7; f++) o[f] = w[f] - m - l;
}

// ---------------- launch ----------------
// Inputs identified BY ELEMENT COUNT (x largest, edge_index second largest,
// W1=8192, W2=112, b1=16, b2=7); positional fallback otherwise.
extern "C" void kernel_launch(void* const* d_in, const int* in_sizes, int n_in,
                              void* d_out, int out_size) {
    const void* x  = d_in[0];
    const void* ei = d_in[1];
    const void* W1 = d_in[2];
    const void* b1 = d_in[3];
    const void* W2 = d_in[4];
    const void* b2 = d_in[5];
    int x_sz = in_sizes[0], e_sz = in_sizes[1];

    if (n_in >= 6) {
        int ix = 0;
        for (int i = 1; i < n_in; i++) if (in_sizes[i] > in_sizes[ix]) ix = i;
        int ie = (ix == 0) ? 1 : 0;
        for (int i = 0; i < n_in; i++)
            if (i != ix && in_sizes[i] > in_sizes[ie]) ie = i;
        x = d_in[ix]; x_sz = in_sizes[ix];
        ei = d_in[ie]; e_sz = in_sizes[ie];
        for (int i = 0; i < n_in; i++) {
            if (i == ix || i == ie) continue;
            switch (in_sizes[i]) {
                case 8192: W1 = d_in[i]; break;   // 512*16
                case 112:  W2 = d_in[i]; break;   // 16*7
                case 16:   b1 = d_in[i]; break;
                case 7:    b2 = d_in[i]; break;
                default: break;
            }
        }
    }

    int n = x_sz / FIN;   // 100000
    int E = e_sz / 2;     // 3200000 edges (planar [src | dst])

    const int T = 256;
    int gbN  = (n + T - 1) / T;              // 391
    int gbG  = gbN;                          // gemm-role blocks
    int gbD  = (E + T - 1) / T;              // deg-role blocks
    int gbE2 = ((E + 1) / 2 + T - 1) / T;    // 2 edges/thread

    k_front<<<gbG + gbD, T>>>((const float*)x, (const float*)W1, ei, n, E, gbG);
    k_scale<<<gbN, T>>>(n);
    k_scatter1<<<gbE2, T>>>(ei, E, n);
    k_layer2<<<gbN, T>>>((const float*)W2, (const float*)b1, n);
    k_scatter2<<<gbE2, T>>>(ei, E, n);
    k_logsoftmax<<<gbN, T>>>((const float*)b2, (float*)d_out, n);
}